// round 6
// baseline (speedup 1.0000x reference)
#include <cuda_runtime.h>
#include <cstdint>

#define BDIM 64
#define TDIM 2048
#define DDIM 256
#define HDIM 256
#define G3   768

__device__ float g_xg[(size_t)BDIM * TDIM * G3];

// ---------------- f32x2 helpers ----------------
__device__ __forceinline__ unsigned long long pk2(float x, float y) {
    unsigned long long r;
    asm("mov.b64 %0, {%1, %2};" : "=l"(r) : "f"(x), "f"(y));
    return r;
}
__device__ __forceinline__ void upk2(unsigned long long p, float& x, float& y) {
    asm("mov.b64 {%0, %1}, %2;" : "=f"(x), "=f"(y) : "l"(p));
}
__device__ __forceinline__ unsigned long long fma2(unsigned long long a,
                                                   unsigned long long b,
                                                   unsigned long long c) {
    unsigned long long d;
    asm("fma.rn.f32x2 %0, %1, %2, %3;" : "=l"(d) : "l"(a), "l"(b), "l"(c));
    return d;
}

// ---------------- Kernel 1: projection GEMM (unchanged, known-good) ----------------
#define BM 64
#define BN 64
#define BK 32

__global__ __launch_bounds__(256) void proj_gemm(const float* __restrict__ x,
                                                 const float* __restrict__ W,
                                                 const float* __restrict__ bias) {
    __shared__ float As[BK][BM + 4];
    __shared__ float Bs[BK][BN + 4];
    const int tid = threadIdx.x;
    const int gm = blockIdx.x * BM;
    const int gn = blockIdx.y * BN;
    const int m4 = (tid >> 4) * 4;
    const int n4 = (tid & 15) * 4;

    unsigned long long acc[4][2];
#pragma unroll
    for (int i = 0; i < 4; i++) { acc[i][0] = 0ull; acc[i][1] = 0ull; }

    for (int kt = 0; kt < DDIM; kt += BK) {
#pragma unroll
        for (int j = 0; j < 2; j++) {
            int idx = tid + j * 256;
            int row = idx >> 3;
            int c4  = (idx & 7) * 4;
            float4 va = *(const float4*)&x[(size_t)(gm + row) * DDIM + kt + c4];
            As[c4 + 0][row] = va.x; As[c4 + 1][row] = va.y;
            As[c4 + 2][row] = va.z; As[c4 + 3][row] = va.w;
            float4 vb = *(const float4*)&W[(size_t)(gn + row) * DDIM + kt + c4];
            Bs[c4 + 0][row] = vb.x; Bs[c4 + 1][row] = vb.y;
            Bs[c4 + 2][row] = vb.z; Bs[c4 + 3][row] = vb.w;
        }
        __syncthreads();
#pragma unroll
        for (int k = 0; k < BK; k++) {
            float4 av = *(const float4*)&As[k][m4];
            float4 bv = *(const float4*)&Bs[k][n4];
            unsigned long long bp0 = pk2(bv.x, bv.y);
            unsigned long long bp1 = pk2(bv.z, bv.w);
            unsigned long long aa;
            aa = pk2(av.x, av.x);
            acc[0][0] = fma2(aa, bp0, acc[0][0]); acc[0][1] = fma2(aa, bp1, acc[0][1]);
            aa = pk2(av.y, av.y);
            acc[1][0] = fma2(aa, bp0, acc[1][0]); acc[1][1] = fma2(aa, bp1, acc[1][1]);
            aa = pk2(av.z, av.z);
            acc[2][0] = fma2(aa, bp0, acc[2][0]); acc[2][1] = fma2(aa, bp1, acc[2][1]);
            aa = pk2(av.w, av.w);
            acc[3][0] = fma2(aa, bp0, acc[3][0]); acc[3][1] = fma2(aa, bp1, acc[3][1]);
        }
        __syncthreads();
    }

    float4 bb = *(const float4*)&bias[gn + n4];
#pragma unroll
    for (int mi = 0; mi < 4; mi++) {
        float o0, o1, o2, o3;
        upk2(acc[mi][0], o0, o1);
        upk2(acc[mi][1], o2, o3);
        float4 o = make_float4(o0 + bb.x, o1 + bb.y, o2 + bb.z, o3 + bb.w);
        *(float4*)&g_xg[(size_t)(gm + m4 + mi) * G3 + gn + n4] = o;
    }
}

// ---------------- Kernel 2: CLSZ=4, register W, mbarrier cluster sync ----------------
#define CLSZ 4
#define RTH  384
#define IDXC 64
#define NROW 192
#define BB   2

__device__ __forceinline__ float sigm_f(float x) { return 1.f / (1.f + __expf(-x)); }
__device__ __forceinline__ float tanh_f(float x) { return 1.f - 2.f / (__expf(2.f * x) + 1.f); }

__device__ __forceinline__ void st_dsmem_u64(uint32_t saddr, uint32_t rk, unsigned long long v) {
    uint32_t ra;
    asm volatile("mapa.shared::cluster.u32 %0, %1, %2;" : "=r"(ra) : "r"(saddr), "r"(rk));
    asm volatile("st.shared::cluster.u64 [%0], %1;" :: "r"(ra), "l"(v) : "memory");
}
__device__ __forceinline__ void arrive_remote(uint32_t lmbar, uint32_t rk) {
    uint32_t ra;
    asm volatile("mapa.shared::cluster.u32 %0, %1, %2;" : "=r"(ra) : "r"(lmbar), "r"(rk));
    asm volatile("mbarrier.arrive.release.cluster.shared::cluster.b64 _, [%0];"
                 :: "r"(ra) : "memory");
}
__device__ __forceinline__ void mbar_wait_acq(uint32_t mbar, uint32_t parity) {
    uint32_t done;
    asm volatile("{\n\t.reg .pred p;\n\t"
                 "mbarrier.try_wait.parity.acquire.cluster.shared::cta.b64 p, [%1], %2;\n\t"
                 "selp.b32 %0, 1, 0, p;\n\t}"
                 : "=r"(done) : "r"(mbar), "r"(parity) : "memory");
    while (!done) {
        asm volatile("{\n\t.reg .pred p;\n\t"
                     "mbarrier.try_wait.parity.acquire.cluster.shared::cta.b64 p, [%1], %2, 0x989680;\n\t"
                     "selp.b32 %0, 1, 0, p;\n\t}"
                     : "=r"(done) : "r"(mbar), "r"(parity) : "memory");
    }
}
__device__ __forceinline__ void cluster_barrier() {
    asm volatile("barrier.cluster.arrive.aligned;" ::: "memory");
    asm volatile("barrier.cluster.wait.aligned;" ::: "memory");
}

__global__ __launch_bounds__(RTH, 1) void gru_rec(const float* __restrict__ h0,
                                                  const float* __restrict__ W_hh,
                                                  const float* __restrict__ b_hh,
                                                  float* __restrict__ hs,
                                                  float* __restrict__ hT) {
    __shared__ alignas(16) float sh_h[2][BB * HDIM];     // [buf][b][k]
    __shared__ alignas(16) float2 sh_hgA[NROW];          // kh=0 partials (b0,b1)
    __shared__ alignas(16) float2 sh_hgB[NROW];          // kh=1 partials (b0,b1)
    __shared__ alignas(8)  unsigned long long sh_mbar[2];

    uint32_t rank; asm("mov.u32 %0, %%cluster_ctarank;" : "=r"(rank));
    const int tid = threadIdx.x;
    const int cb = (blockIdx.x >> 2) * BB;

    const int kh = tid >= NROW;            // k-half
    const int r  = tid - kh * NROW;        // row 0..191
    const int g  = r >> 6, il = r & 63;
    const int grow = g * HDIM + (int)rank * IDXC + il;

    // ---- W slice -> 64 packed f32x2 registers; wq[m] covers k = 2m, 2m+1 (within k-half)
    unsigned long long wq[64];
    {
        const ulonglong2* wp = (const ulonglong2*)(W_hh + (size_t)grow * HDIM + kh * 128);
#pragma unroll
        for (int j = 0; j < 32; j++) { ulonglong2 u = wp[j]; wq[2*j] = u.x; wq[2*j+1] = u.y; }
    }
    // ---- gate-thread biases (tid<128: b = tid>>6, gil = tid&63)
    float bhr = 0.f, bhz = 0.f, bhn = 0.f;
    if (tid < 128) {
        int gil = tid & 63, gi = (int)rank * IDXC + gil;
        bhr = b_hh[gi]; bhz = b_hh[HDIM + gi]; bhn = b_hh[2 * HDIM + gi];
    }
    // ---- h0 -> buffer 0; init mbarriers
    for (int i = tid; i < BB * HDIM; i += RTH) {
        int b = i >> 8, k = i & 255;
        sh_h[0][i] = h0[(size_t)(cb + b) * HDIM + k];
    }
    const uint32_t mbar_s = (uint32_t)__cvta_generic_to_shared(sh_mbar);
    if (tid == 0) {
        asm volatile("mbarrier.init.shared.b64 [%0], %1;" :: "r"(mbar_s),     "r"((uint32_t)CLSZ) : "memory");
        asm volatile("mbarrier.init.shared.b64 [%0], %1;" :: "r"(mbar_s + 8), "r"((uint32_t)CLSZ) : "memory");
    }
    __syncthreads();
    cluster_barrier();   // publish mbarrier init + h0 before any remote traffic

    // gate-thread xg base: address of xr for (b, gi); xz at +256, xn at +512
    const int gb = tid >> 6, ggil = tid & 63;
    const size_t xg_gate_base = ((size_t)(cb + gb) * TDIM) * G3
                              + (size_t)rank * IDXC + ggil;

    const uint32_t h_s = (uint32_t)__cvta_generic_to_shared(sh_h);
    int ph0 = 0, ph1 = 0;

    for (int t = 0; t < TDIM; t++) {
        const int cur = t & 1;

        // prefetch xg (gate threads only) before waiting
        float xr = 0.f, xz = 0.f, xn = 0.f;
        if (tid < 128) {
            const float* xp = g_xg + xg_gate_base + (size_t)t * G3;
            xr = xp[0]; xz = xp[256]; xn = xp[512];
        }

        if (t > 0) {
            if (cur == 0) { mbar_wait_acq(mbar_s, (uint32_t)ph0); ph0 ^= 1; }
            else          { mbar_wait_acq(mbar_s + 8, (uint32_t)ph1); ph1 ^= 1; }
        }
        const float* hb = sh_h[cur];

        // matvec: 4 independent fma2 chains (2 per batch)
        const ulonglong2* hpA = (const ulonglong2*)(hb + kh * 128);
        const ulonglong2* hpB = (const ulonglong2*)(hb + HDIM + kh * 128);
        unsigned long long a0a = 0ull, a0b = 0ull, a1a = 0ull, a1b = 0ull;
#pragma unroll
        for (int c = 0; c < 16; c++) {
            ulonglong2 vA = hpA[c];
            a0a = fma2(wq[2*c+0], vA.x, a0a); a0a = fma2(wq[2*c+1], vA.y, a0a);
            ulonglong2 vB = hpB[c];
            a1a = fma2(wq[2*c+0], vB.x, a1a); a1a = fma2(wq[2*c+1], vB.y, a1a);
            ulonglong2 vA2 = hpA[16 + c];
            a0b = fma2(wq[32+2*c+0], vA2.x, a0b); a0b = fma2(wq[32+2*c+1], vA2.y, a0b);
            ulonglong2 vB2 = hpB[16 + c];
            a1b = fma2(wq[32+2*c+0], vB2.x, a1b); a1b = fma2(wq[32+2*c+1], vB2.y, a1b);
        }
        float s0, s1, xl, xh2;
        unsigned long long t0 = fma2(pk2(1.f, 1.f), a0a, a0b);  // (lo+lo, hi+hi)
        upk2(t0, xl, xh2); s0 = xl + xh2;
        unsigned long long t1 = fma2(pk2(1.f, 1.f), a1a, a1b);
        upk2(t1, xl, xh2); s1 = xl + xh2;
        if (kh) sh_hgB[r] = make_float2(s0, s1);
        else    sh_hgA[r] = make_float2(s0, s1);
        __syncthreads();

        if (tid < 128) {
            const int b = gb, gil = ggil;
            const int gi = (int)rank * IDXC + gil;
            float2 rA = sh_hgA[gil],        rB = sh_hgB[gil];
            float2 zA = sh_hgA[64 + gil],   zB = sh_hgB[64 + gil];
            float2 nA = sh_hgA[128 + gil],  nB = sh_hgB[128 + gil];
            float hr  = b ? (rA.y + rB.y) : (rA.x + rB.x);
            float hz  = b ? (zA.y + zB.y) : (zA.x + zB.x);
            float hnv = b ? (nA.y + nB.y) : (nA.x + nB.x);
            float hprev = hb[b * HDIM + gi];
            float rg = sigm_f(xr + hr + bhr);
            float zg = sigm_f(xz + hz + bhz);
            float ng = tanh_f(xn + rg * (hnv + bhn));
            float hnew = (1.f - zg) * ng + zg * hprev;

            float hpart = __shfl_down_sync(0xffffffffu, hnew, 1);
            if ((gil & 1) == 0) {
                // pair-store hs (STG.64)
                *(float2*)&hs[((size_t)(cb + b) * TDIM + t) * HDIM + gi] = make_float2(hnew, hpart);
                if (t < TDIM - 1) {
                    unsigned long long pv = pk2(hnew, hpart);
                    uint32_t laddr = h_s + 4u * (uint32_t)((cur ^ 1) * (BB * HDIM) + b * HDIM + gi);
#pragma unroll
                    for (uint32_t dr = 0; dr < CLSZ; dr++) st_dsmem_u64(laddr, dr, pv);
                }
            }
            if (t == TDIM - 1) hT[(size_t)(cb + b) * HDIM + gi] = hnew;

            if (t < TDIM - 1) {
                // gate-warp barrier: all gate-thread DSMEM stores issued before signaling
                asm volatile("bar.sync 1, 128;" ::: "memory");
                if (tid < CLSZ) arrive_remote(mbar_s + (uint32_t)(cur ^ 1) * 8u, (uint32_t)tid);
            }
        }
        // Non-gate threads proceed; next-step mbar wait (requires own CTA's arrive)
        // orders their buffer/partial-array writes after this step's gate reads.
    }

    cluster_barrier();   // keep smem alive until all peers' last DSMEM ops done
}

// ---------------- launch ----------------
extern "C" void kernel_launch(void* const* d_in, const int* in_sizes, int n_in,
                              void* d_out, int out_size) {
    (void)in_sizes; (void)n_in; (void)out_size;
    const float* x    = (const float*)d_in[0];
    const float* h0   = (const float*)d_in[1];
    const float* W_ih = (const float*)d_in[2];
    const float* W_hh = (const float*)d_in[3];
    const float* b_ih = (const float*)d_in[4];
    const float* b_hh = (const float*)d_in[5];
    float* out = (float*)d_out;
    float* hs = out;
    float* hT = out + (size_t)BDIM * TDIM * HDIM;

    dim3 g1((BDIM * TDIM) / BM, G3 / BN);
    proj_gemm<<<g1, 256>>>(x, W_ih, b_ih);

    cudaLaunchConfig_t cfg = {};
    cfg.gridDim = dim3(32 * CLSZ, 1, 1);
    cfg.blockDim = dim3(RTH, 1, 1);
    cfg.dynamicSmemBytes = 0;
    cfg.stream = 0;
    cudaLaunchAttribute attrs[1];
    attrs[0].id = cudaLaunchAttributeClusterDimension;
    attrs[0].val.clusterDim.x = CLSZ;
    attrs[0].val.clusterDim.y = 1;
    attrs[0].val.clusterDim.z = 1;
    cfg.attrs = attrs;
    cfg.numAttrs = 1;
    cudaLaunchKernelEx(&cfg, gru_rec, h0, W_hh, b_hh, hs, hT);
}

// round 7
// speedup vs baseline: 1.1976x; 1.1976x over previous
#include <cuda_runtime.h>
#include <cstdint>

#define BDIM 64
#define TDIM 2048
#define DDIM 256
#define HDIM 256
#define G3   768

__device__ float g_xg[(size_t)BDIM * TDIM * G3];

// ---------------- f32x2 helpers ----------------
__device__ __forceinline__ unsigned long long pk2(float x, float y) {
    unsigned long long r;
    asm("mov.b64 %0, {%1, %2};" : "=l"(r) : "f"(x), "f"(y));
    return r;
}
__device__ __forceinline__ void upk2(unsigned long long p, float& x, float& y) {
    asm("mov.b64 {%0, %1}, %2;" : "=f"(x), "=f"(y) : "l"(p));
}
__device__ __forceinline__ unsigned long long fma2(unsigned long long a,
                                                   unsigned long long b,
                                                   unsigned long long c) {
    unsigned long long d;
    asm("fma.rn.f32x2 %0, %1, %2, %3;" : "=l"(d) : "l"(a), "l"(b), "l"(c));
    return d;
}

// ---------------- Kernel 1: projection GEMM (unchanged, known-good) ----------------
#define BM 64
#define BN 64
#define BK 32

__global__ __launch_bounds__(256) void proj_gemm(const float* __restrict__ x,
                                                 const float* __restrict__ W,
                                                 const float* __restrict__ bias) {
    __shared__ float As[BK][BM + 4];
    __shared__ float Bs[BK][BN + 4];
    const int tid = threadIdx.x;
    const int gm = blockIdx.x * BM;
    const int gn = blockIdx.y * BN;
    const int m4 = (tid >> 4) * 4;
    const int n4 = (tid & 15) * 4;

    unsigned long long acc[4][2];
#pragma unroll
    for (int i = 0; i < 4; i++) { acc[i][0] = 0ull; acc[i][1] = 0ull; }

    for (int kt = 0; kt < DDIM; kt += BK) {
#pragma unroll
        for (int j = 0; j < 2; j++) {
            int idx = tid + j * 256;
            int row = idx >> 3;
            int c4  = (idx & 7) * 4;
            float4 va = *(const float4*)&x[(size_t)(gm + row) * DDIM + kt + c4];
            As[c4 + 0][row] = va.x; As[c4 + 1][row] = va.y;
            As[c4 + 2][row] = va.z; As[c4 + 3][row] = va.w;
            float4 vb = *(const float4*)&W[(size_t)(gn + row) * DDIM + kt + c4];
            Bs[c4 + 0][row] = vb.x; Bs[c4 + 1][row] = vb.y;
            Bs[c4 + 2][row] = vb.z; Bs[c4 + 3][row] = vb.w;
        }
        __syncthreads();
#pragma unroll
        for (int k = 0; k < BK; k++) {
            float4 av = *(const float4*)&As[k][m4];
            float4 bv = *(const float4*)&Bs[k][n4];
            unsigned long long bp0 = pk2(bv.x, bv.y);
            unsigned long long bp1 = pk2(bv.z, bv.w);
            unsigned long long aa;
            aa = pk2(av.x, av.x);
            acc[0][0] = fma2(aa, bp0, acc[0][0]); acc[0][1] = fma2(aa, bp1, acc[0][1]);
            aa = pk2(av.y, av.y);
            acc[1][0] = fma2(aa, bp0, acc[1][0]); acc[1][1] = fma2(aa, bp1, acc[1][1]);
            aa = pk2(av.z, av.z);
            acc[2][0] = fma2(aa, bp0, acc[2][0]); acc[2][1] = fma2(aa, bp1, acc[2][1]);
            aa = pk2(av.w, av.w);
            acc[3][0] = fma2(aa, bp0, acc[3][0]); acc[3][1] = fma2(aa, bp1, acc[3][1]);
        }
        __syncthreads();
    }

    float4 bb = *(const float4*)&bias[gn + n4];
#pragma unroll
    for (int mi = 0; mi < 4; mi++) {
        float o0, o1, o2, o3;
        upk2(acc[mi][0], o0, o1);
        upk2(acc[mi][1], o2, o3);
        float4 o = make_float4(o0 + bb.x, o1 + bb.y, o2 + bb.z, o3 + bb.w);
        *(float4*)&g_xg[(size_t)(gm + m4 + mi) * G3 + gn + n4] = o;
    }
}

// ---------------- Kernel 2: CLSZ=4, register W, cluster barrier (arrive/wait split) ----------------
#define CLSZ 4
#define RTH  384
#define IDXC 64
#define NROW 192
#define BB   2

__device__ __forceinline__ float sigm_f(float x) { return 1.f / (1.f + __expf(-x)); }
__device__ __forceinline__ float tanh_f(float x) { return 1.f - 2.f / (__expf(2.f * x) + 1.f); }

__device__ __forceinline__ void st_dsmem_u64(uint32_t saddr, uint32_t rk, unsigned long long v) {
    uint32_t ra;
    asm volatile("mapa.shared::cluster.u32 %0, %1, %2;" : "=r"(ra) : "r"(saddr), "r"(rk));
    asm volatile("st.shared::cluster.u64 [%0], %1;" :: "r"(ra), "l"(v) : "memory");
}
__device__ __forceinline__ void cluster_arrive() {
    asm volatile("barrier.cluster.arrive.aligned;" ::: "memory");
}
__device__ __forceinline__ void cluster_wait() {
    asm volatile("barrier.cluster.wait.aligned;" ::: "memory");
}

__global__ __launch_bounds__(RTH, 1) void gru_rec(const float* __restrict__ h0,
                                                  const float* __restrict__ W_hh,
                                                  const float* __restrict__ b_hh,
                                                  float* __restrict__ hs,
                                                  float* __restrict__ hT) {
    __shared__ alignas(16) float sh_h[2][BB * HDIM];     // [buf][b][k]
    __shared__ alignas(16) float2 sh_hgA[NROW];          // kh=0 partials (b0,b1)
    __shared__ alignas(16) float2 sh_hgB[NROW];          // kh=1 partials (b0,b1)

    uint32_t rank; asm("mov.u32 %0, %%cluster_ctarank;" : "=r"(rank));
    const int tid = threadIdx.x;
    const int cb = (blockIdx.x >> 2) * BB;

    const int kh = tid >= NROW;            // k-half
    const int r  = tid - kh * NROW;        // row 0..191
    const int g  = r >> 6, il = r & 63;
    const int grow = g * HDIM + (int)rank * IDXC + il;

    // ---- W slice -> 64 packed f32x2 registers; wq[m] covers k = 2m, 2m+1 (within k-half)
    unsigned long long wq[64];
    {
        const ulonglong2* wp = (const ulonglong2*)(W_hh + (size_t)grow * HDIM + kh * 128);
#pragma unroll
        for (int j = 0; j < 32; j++) { ulonglong2 u = wp[j]; wq[2*j] = u.x; wq[2*j+1] = u.y; }
    }
    // ---- gate-thread biases (tid<128: b = tid>>6, gil = tid&63)
    float bhr = 0.f, bhz = 0.f, bhn = 0.f;
    if (tid < 128) {
        int gil = tid & 63, gi = (int)rank * IDXC + gil;
        bhr = b_hh[gi]; bhz = b_hh[HDIM + gi]; bhn = b_hh[2 * HDIM + gi];
    }
    // ---- h0 -> buffer 0
    for (int i = tid; i < BB * HDIM; i += RTH) {
        int b = i >> 8, k = i & 255;
        sh_h[0][i] = h0[(size_t)(cb + b) * HDIM + k];
    }
    __syncthreads();
    cluster_arrive();
    cluster_wait();

    // gate-thread xg base: address of xr for (b, gi); xz at +256, xn at +512
    const int gb = tid >> 6, ggil = tid & 63;
    const size_t xg_gate_base = ((size_t)(cb + gb) * TDIM) * G3
                              + (size_t)rank * IDXC + ggil;

    const uint32_t h_s = (uint32_t)__cvta_generic_to_shared(sh_h);

    for (int t = 0; t < TDIM; t++) {
        const int cur = t & 1;
        const float* hb = sh_h[cur];

        // prefetch xg (gate threads only) — hidden under the matvec
        float xr = 0.f, xz = 0.f, xn = 0.f;
        if (tid < 128) {
            const float* xp = g_xg + xg_gate_base + (size_t)t * G3;
            xr = xp[0]; xz = xp[256]; xn = xp[512];
        }

        // matvec: 4 independent fma2 chains (2 per batch)
        const ulonglong2* hpA = (const ulonglong2*)(hb + kh * 128);
        const ulonglong2* hpB = (const ulonglong2*)(hb + HDIM + kh * 128);
        unsigned long long a0a = 0ull, a0b = 0ull, a1a = 0ull, a1b = 0ull;
#pragma unroll
        for (int c = 0; c < 16; c++) {
            ulonglong2 vA = hpA[c];
            a0a = fma2(wq[2*c+0], vA.x, a0a); a0a = fma2(wq[2*c+1], vA.y, a0a);
            ulonglong2 vB = hpB[c];
            a1a = fma2(wq[2*c+0], vB.x, a1a); a1a = fma2(wq[2*c+1], vB.y, a1a);
            ulonglong2 vA2 = hpA[16 + c];
            a0b = fma2(wq[32+2*c+0], vA2.x, a0b); a0b = fma2(wq[32+2*c+1], vA2.y, a0b);
            ulonglong2 vB2 = hpB[16 + c];
            a1b = fma2(wq[32+2*c+0], vB2.x, a1b); a1b = fma2(wq[32+2*c+1], vB2.y, a1b);
        }
        float s0, s1, xl, xh2;
        unsigned long long t0 = fma2(pk2(1.f, 1.f), a0a, a0b);  // (lo+lo, hi+hi)
        upk2(t0, xl, xh2); s0 = xl + xh2;
        unsigned long long t1 = fma2(pk2(1.f, 1.f), a1a, a1b);
        upk2(t1, xl, xh2); s1 = xl + xh2;
        if (kh) sh_hgB[r] = make_float2(s0, s1);
        else    sh_hgA[r] = make_float2(s0, s1);
        __syncthreads();

        float hnew = 0.f, hpart = 0.f;
        int b = gb, gi = (int)rank * IDXC + ggil;
        if (tid < 128) {
            const int gil = ggil;
            float2 rA = sh_hgA[gil],        rB = sh_hgB[gil];
            float2 zA = sh_hgA[64 + gil],   zB = sh_hgB[64 + gil];
            float2 nA = sh_hgA[128 + gil],  nB = sh_hgB[128 + gil];
            float hr  = b ? (rA.y + rB.y) : (rA.x + rB.x);
            float hz  = b ? (zA.y + zB.y) : (zA.x + zB.x);
            float hnv = b ? (nA.y + nB.y) : (nA.x + nB.x);
            float hprev = hb[b * HDIM + gi];
            float rg = sigm_f(xr + hr + bhr);
            float zg = sigm_f(xz + hz + bhz);
            float ng = tanh_f(xn + rg * (hnv + bhn));
            hnew = (1.f - zg) * ng + zg * hprev;

            hpart = __shfl_down_sync(0xffffffffu, hnew, 1);
            if (t < TDIM - 1 && (ggil & 1) == 0) {
                unsigned long long pv = pk2(hnew, hpart);
                uint32_t laddr = h_s + 4u * (uint32_t)((cur ^ 1) * (BB * HDIM) + b * HDIM + gi);
#pragma unroll
                for (uint32_t dr = 0; dr < CLSZ; dr++) st_dsmem_u64(laddr, dr, pv);
            }
        }
        // arrive releases the DSMEM stores; STGs overlap the barrier wait
        cluster_arrive();
        if (tid < 128) {
            if ((ggil & 1) == 0)
                *(float2*)&hs[((size_t)(cb + b) * TDIM + t) * HDIM + gi] = make_float2(hnew, hpart);
            if (t == TDIM - 1) hT[(size_t)(cb + b) * HDIM + gi] = hnew;
        }
        cluster_wait();
    }
}

// ---------------- launch ----------------
extern "C" void kernel_launch(void* const* d_in, const int* in_sizes, int n_in,
                              void* d_out, int out_size) {
    (void)in_sizes; (void)n_in; (void)out_size;
    const float* x    = (const float*)d_in[0];
    const float* h0   = (const float*)d_in[1];
    const float* W_ih = (const float*)d_in[2];
    const float* W_hh = (const float*)d_in[3];
    const float* b_ih = (const float*)d_in[4];
    const float* b_hh = (const float*)d_in[5];
    float* out = (float*)d_out;
    float* hs = out;
    float* hT = out + (size_t)BDIM * TDIM * HDIM;

    dim3 g1((BDIM * TDIM) / BM, G3 / BN);
    proj_gemm<<<g1, 256>>>(x, W_ih, b_ih);

    cudaLaunchConfig_t cfg = {};
    cfg.gridDim = dim3(32 * CLSZ, 1, 1);
    cfg.blockDim = dim3(RTH, 1, 1);
    cfg.dynamicSmemBytes = 0;
    cfg.stream = 0;
    cudaLaunchAttribute attrs[1];
    attrs[0].id = cudaLaunchAttributeClusterDimension;
    attrs[0].val.clusterDim.x = CLSZ;
    attrs[0].val.clusterDim.y = 1;
    attrs[0].val.clusterDim.z = 1;
    cfg.attrs = attrs;
    cfg.numAttrs = 1;
    cudaLaunchKernelEx(&cfg, gru_rec, h0, W_hh, b_hh, hs, hT);
}